// round 16
// baseline (speedup 1.0000x reference)
#include <cuda_runtime.h>
#include <cuda_fp16.h>
#include <cstdint>

#define DINLINE __device__ __forceinline__

constexpr int NPTS   = 100000;
constexpr int NPAIRS = 50000;
constexpr int KOFF   = 27;
constexpr int C      = 128;
constexpr int TILE_M = 128;
constexpr int NTILES = (NPAIRS + TILE_M - 1) / TILE_M;    // 391
constexpr int JT     = KOFF * NTILES;                     // 10557 jobs
constexpr int NCTA   = 148;                               // 1 CTA/SM, full chip
constexpr int JBASE  = JT / NCTA;                         // 71
constexpr int JREM   = JT % NCTA;                         // 49
constexpr int THREADS = 512;                              // 16 warps -> 4/SMSP
constexpr int ROWW   = 68;                                // fp16 words32/row (64 data + 4 pad)
constexpr int FBUF   = TILE_M * ROWW;                     // 8704 words per fp16 buffer
constexpr int SBUF   = TILE_M * C;                        // 16384 words per fp32 staging buffer

// scratch: intermediate activations + pre-transposed fp16 weights
__device__ float  g_h[(size_t)NPTS * C];
__device__ __half g_Wh[(size_t)2 * KOFF * C * C];         // [conv][k][n][c], fp16

// ---------------------------------------------------------------- helpers
DINLINE void red_add_v4(float* a, float x, float y, float z, float w) {
    asm volatile("red.global.add.v4.f32 [%0], {%1,%2,%3,%4};"
                 :: "l"(a), "f"(x), "f"(y), "f"(z), "f"(w) : "memory");
}
DINLINE void cp_async16(uint32_t dst_smem, const void* src) {
    asm volatile("cp.async.ca.shared.global [%0], [%1], 16;"
                 :: "r"(dst_smem), "l"(src) : "memory");
}
DINLINE void cp_commit() { asm volatile("cp.async.commit_group;" ::: "memory"); }
DINLINE void cp_wait0()  { asm volatile("cp.async.wait_group 0;" ::: "memory"); }
// m16n8k16 fp16 mma: A row-major frag {a0..a3}, B col-major frag {b0,b1}, fp32 acc
DINLINE void mma_f16(float c[4], uint32_t a0, uint32_t a1, uint32_t a2, uint32_t a3,
                     uint32_t b0, uint32_t b1) {
    asm volatile(
        "mma.sync.aligned.m16n8k16.row.col.f32.f16.f16.f32 "
        "{%0,%1,%2,%3}, {%4,%5,%6,%7}, {%8,%9}, {%0,%1,%2,%3};"
        : "+f"(c[0]), "+f"(c[1]), "+f"(c[2]), "+f"(c[3])
        : "r"(a0), "r"(a1), "r"(a2), "r"(a3), "r"(b0), "r"(b1));
}

// issue async gather of tile t into fp32 staging (8 threads/row, 4 lines/instr)
DINLINE void issue_gather(uint32_t* stage, const float* __restrict__ X,
                          const int* __restrict__ im, int t, int gr, int ge) {
    #pragma unroll
    for (int pp = 0; pp < 2; pp++) {
        int r  = pp * 64 + gr;
        int p  = t * TILE_M + r;
        int pv = p < NPAIRS ? p : NPAIRS - 1;     // clamp; invalid rows never scattered
        const float* src = X + (size_t)im[pv] * C;
        uint32_t dst = (uint32_t)__cvta_generic_to_shared(stage + r * C);
        #pragma unroll
        for (int jj = 0; jj < 4; jj++) {
            int f4 = ge + 8 * jj;
            cp_async16(dst + 16 * f4, src + 4 * f4);
        }
    }
}

// convert own staged rows: fp32 -> (relu) -> fp16, into padded fp16 tile
DINLINE void convert_tile(const uint32_t* stage, uint32_t* fbuf,
                          int do_relu, int gr, int ge) {
    #pragma unroll
    for (int pp = 0; pp < 2; pp++) {
        int r = pp * 64 + gr;
        const float4* srow = reinterpret_cast<const float4*>(stage + r * C);
        uint32_t* drow = fbuf + r * ROWW;
        #pragma unroll
        for (int jj = 0; jj < 4; jj++) {
            int f4 = ge + 8 * jj;
            float4 v = srow[f4];
            if (do_relu) {
                v.x = fmaxf(v.x, 0.f); v.y = fmaxf(v.y, 0.f);
                v.z = fmaxf(v.z, 0.f); v.w = fmaxf(v.w, 0.f);
            }
            __half2 h01 = __floats2half2_rn(v.x, v.y);
            __half2 h23 = __floats2half2_rn(v.z, v.w);
            uint2 o;
            o.x = *reinterpret_cast<uint32_t*>(&h01);
            o.y = *reinterpret_cast<uint32_t*>(&h23);
            *reinterpret_cast<uint2*>(drow + 2 * f4) = o;
        }
    }
}

// ---------------------------------------------------------------- main kernel
// 148 persistent CTAs over (k, tile) jobs, contiguous blocks (<=1 W reload/CTA).
// 512 threads, 16 warps in 4(row-quarter) x 4(col-quarter): warp owns 32 rows x
// 32 cols. fp16 B fragments (64 regs) resident. Pipeline per tile:
//   cp.async.wait0 -> convert own staged data (fp32->fp16, relu) -> issue
//   cp.async for next tile -> __syncthreads -> MMA + scatter.
// One barrier per tile; gather latency fully async; 4 warps/SMSP hide LDS/REDG.
// fp16 tile rows padded to 68 words: MMA-read bank = (4g + tig) mod 32, all 32
// lanes distinct. Scatter: quad butterfly -> red.global.add.v4.
__global__ void __launch_bounds__(THREADS, 1)
spconv_mma_kernel(const float* __restrict__ X,
                  const __half* __restrict__ Wh,    // [KOFF][n][c], fp16
                  const int* __restrict__ in_map,
                  const int* __restrict__ out_map,
                  float* __restrict__ Y,
                  int do_relu)
{
    extern __shared__ __align__(16) uint32_t SM[];
    uint32_t* fb[2] = { SM, SM + FBUF };
    uint32_t* st[2] = { SM + 2 * FBUF, SM + 2 * FBUF + SBUF };

    const int tid = threadIdx.x;
    const int wid = tid >> 5, lid = tid & 31;
    const int g = lid >> 2, tig = lid & 3;         // groupID / thread-in-group
    const int rq = wid >> 2;                       // row quarter (0..3)
    const int n0 = (wid & 3) * 32;                 // col quarter base
    const int gr = tid >> 3, ge = tid & 7;         // gather/convert role

    const int cta  = blockIdx.x;
    const int jbeg = cta * JBASE + (cta < JREM ? cta : JREM);
    const int jend = jbeg + JBASE + (cta < JREM ? 1 : 0);

    uint32_t bfr[8][4][2];                         // fp16 B fragments (64 regs)
    int kcur = -1;

    // prologue: async-gather first tile into staging 0
    {
        int k0 = jbeg / NTILES, t0 = jbeg % NTILES;
        issue_gather(st[0], X, in_map + k0 * NPAIRS, t0, gr, ge);
        cp_commit();
    }

    int s = 0, c = 0;
    for (int jid = jbeg; jid < jend; jid++) {
        const int k = jid / NTILES, t = jid % NTILES;

        // ---- (re)load B fragments on k change ----
        if (k != kcur) {
            kcur = k;
            const __half* wk = Wh + (size_t)k * C * C;
            #pragma unroll
            for (int ks = 0; ks < 8; ks++)
                #pragma unroll
                for (int nb = 0; nb < 4; nb++) {
                    const __half* wrow = wk + (n0 + 8 * nb + g) * C + 16 * ks + 2 * tig;
                    bfr[ks][nb][0] = *reinterpret_cast<const uint32_t*>(wrow);
                    bfr[ks][nb][1] = *reinterpret_cast<const uint32_t*>(wrow + 8);
                }
        }

        // ---- wait own copies, convert own rows (no barrier needed: self-data) ----
        cp_wait0();
        convert_tile(st[s], fb[c], do_relu, gr, ge);

        // ---- issue async gather for next tile into the other staging buffer ----
        if (jid + 1 < jend) {
            int k2 = (jid + 1) / NTILES, t2 = (jid + 1) % NTILES;
            issue_gather(st[s ^ 1], X, in_map + k2 * NPAIRS, t2, gr, ge);
            cp_commit();
        }

        __syncthreads();                           // fp16 tile visible to all

        // ---- MMA + scatter on fb[c] ----
        const uint32_t* abuf = fb[c];
        const int* om = out_map + k * NPAIRS;
        #pragma unroll 1
        for (int mb = 0; mb < 2; mb++) {
            float acc[4][4] = {{0.f,0.f,0.f,0.f},{0.f,0.f,0.f,0.f},
                               {0.f,0.f,0.f,0.f},{0.f,0.f,0.f,0.f}};
            const int row_lo = rq * 32 + mb * 16 + g;
            const uint32_t* a_lo = abuf + row_lo * ROWW;
            const uint32_t* a_hi = a_lo + 8 * ROWW;
            #pragma unroll
            for (int ks = 0; ks < 8; ks++) {
                uint32_t a0 = a_lo[ks * 8 + tig];
                uint32_t a1 = a_hi[ks * 8 + tig];
                uint32_t a2 = a_lo[ks * 8 + tig + 4];
                uint32_t a3 = a_hi[ks * 8 + tig + 4];
                #pragma unroll
                for (int nb = 0; nb < 4; nb++)
                    mma_f16(acc[nb], a0, a1, a2, a3, bfr[ks][nb][0], bfr[ks][nb][1]);
            }

            // epilogue: quad butterfly -> red.v4 (16B per lane)
            int p_lo = t * TILE_M + row_lo;
            int p_hi = p_lo + 8;
            int d_lo = (p_lo < NPAIRS) ? om[p_lo] : -1;
            int d_hi = (p_hi < NPAIRS) ? om[p_hi] : -1;
            int dst  = (tig & 1) ? d_hi : d_lo;
            float* ybase = (dst >= 0)
                ? Y + (size_t)dst * C + n0 + ((tig >> 1) << 2) : nullptr;
            #pragma unroll
            for (int nb = 0; nb < 4; nb++) {
                // even lanes need partner's (c0,c1); odd lanes partner's (c2,c3)
                float s0 = (tig & 1) ? acc[nb][0] : acc[nb][2];
                float s1 = (tig & 1) ? acc[nb][1] : acc[nb][3];
                float r0 = __shfl_xor_sync(0xffffffffu, s0, 1);
                float r1 = __shfl_xor_sync(0xffffffffu, s1, 1);
                float q0 = (tig & 1) ? r0 : acc[nb][0];
                float q1 = (tig & 1) ? r1 : acc[nb][1];
                float q2 = (tig & 1) ? acc[nb][2] : r0;
                float q3 = (tig & 1) ? acc[nb][3] : r1;
                if (ybase) red_add_v4(ybase + 8 * nb, q0, q1, q2, q3);
            }
        }
        s ^= 1; c ^= 1;
    }
}

// ---------------------------------------------------------------- small kernels
__global__ void wt_kernel(const float* __restrict__ W0, const float* __restrict__ W1) {
    int i = blockIdx.x * blockDim.x + threadIdx.x;       // over KOFF*C*C, layout [k][n][c]
    if (i >= KOFF * C * C) return;
    int k = i / (C * C);
    int rem = i % (C * C);
    int n = rem / C, c = rem % C;
    g_Wh[i] = __float2half_rn(W0[(size_t)k * C * C + c * C + n]);
    g_Wh[(size_t)KOFF * C * C + i] = __float2half_rn(W1[(size_t)k * C * C + c * C + n]);
}

__global__ void init_h_kernel(const float* __restrict__ b0) {
    int i = blockIdx.x * blockDim.x + threadIdx.x;       // float4 index
    if (i < NPTS * C / 4)
        reinterpret_cast<float4*>(g_h)[i] =
            reinterpret_cast<const float4*>(b0)[i & (C / 4 - 1)];
}

__global__ void init_out_kernel(const float* __restrict__ feat,
                                const float* __restrict__ b1,
                                float* __restrict__ out) {
    int i = blockIdx.x * blockDim.x + threadIdx.x;
    if (i < NPTS * C / 4) {
        float4 f = reinterpret_cast<const float4*>(feat)[i];
        float4 b = reinterpret_cast<const float4*>(b1)[i & (C / 4 - 1)];
        f.x += b.x; f.y += b.y; f.z += b.z; f.w += b.w;
        reinterpret_cast<float4*>(out)[i] = f;
    }
}

// ---------------------------------------------------------------- launch
extern "C" void kernel_launch(void* const* d_in, const int* in_sizes, int n_in,
                              void* d_out, int out_size) {
    const float* feat    = (const float*)d_in[0];
    const int*   in_map  = (const int*)  d_in[1];
    const int*   out_map = (const int*)  d_in[2];
    const float* W0      = (const float*)d_in[3];
    const float* b0      = (const float*)d_in[4];
    const float* W1      = (const float*)d_in[5];
    const float* b1      = (const float*)d_in[6];
    float*       out     = (float*)d_out;

    float*  h  = nullptr; cudaGetSymbolAddress((void**)&h,  g_h);
    __half* wh = nullptr; cudaGetSymbolAddress((void**)&wh, g_Wh);

    const int smem_bytes = (2 * FBUF + 2 * SBUF) * (int)sizeof(uint32_t);  // 200704
    cudaFuncSetAttribute(spconv_mma_kernel,
                         cudaFuncAttributeMaxDynamicSharedMemorySize, smem_bytes);

    const int nv4 = NPTS * C / 4;

    wt_kernel<<<(KOFF * C * C + 255) / 256, 256>>>(W0, W1);

    // conv0: h = b0; h += scatter(gather(x) @ W0)   (relu deferred into conv1's gather)
    init_h_kernel<<<(nv4 + 255) / 256, 256>>>(b0);
    spconv_mma_kernel<<<NCTA, THREADS, smem_bytes>>>(feat, wh, in_map, out_map, h, 0);

    // conv1: out = x + b1; out += scatter(gather(relu(h)) @ W1)
    init_out_kernel<<<(nv4 + 255) / 256, 256>>>(feat, b1, out);
    spconv_mma_kernel<<<NCTA, THREADS, smem_bytes>>>(h, wh + (size_t)KOFF * C * C,
                                                    in_map, out_map, out, 1);
}

// round 17
// speedup vs baseline: 1.5076x; 1.5076x over previous
#include <cuda_runtime.h>
#include <cuda_fp16.h>
#include <cstdint>

#define DINLINE __device__ __forceinline__

constexpr int NPTS   = 100000;
constexpr int NPAIRS = 50000;
constexpr int KOFF   = 27;
constexpr int C      = 128;
constexpr int TILE_M = 128;
constexpr int NTILES = (NPAIRS + TILE_M - 1) / TILE_M;    // 391
constexpr int JT     = KOFF * NTILES;                     // 10557 jobs
constexpr int NCTA   = 296;                               // 2 CTA/SM, full chip
constexpr int JBASE  = JT / NCTA;                         // 35
constexpr int JREM   = JT % NCTA;                         // 197
constexpr int THREADS = 256;
constexpr int ROWW   = 68;                                // words32/row: 64 fp16-data + 4 pad
constexpr int FBUF   = TILE_M * ROWW;                     // 8704 words per fp16 A buffer

// scratch: fp32 intermediate, fp16 activation copies, fp16 transposed weights
__device__ float  g_h[(size_t)NPTS * C];
__device__ __half g_xh0[(size_t)NPTS * C];                // fp16(features)
__device__ __half g_xh1[(size_t)NPTS * C];                // fp16(relu(h))
__device__ __half g_Wh[(size_t)2 * KOFF * C * C];         // [conv][k][n][c], fp16

// ---------------------------------------------------------------- helpers
DINLINE void red_add_v4(float* a, float x, float y, float z, float w) {
    asm volatile("red.global.add.v4.f32 [%0], {%1,%2,%3,%4};"
                 :: "l"(a), "f"(x), "f"(y), "f"(z), "f"(w) : "memory");
}
DINLINE void cp_async16(uint32_t dst_smem, const void* src) {
    asm volatile("cp.async.ca.shared.global [%0], [%1], 16;"
                 :: "r"(dst_smem), "l"(src) : "memory");
}
DINLINE void cp_commit() { asm volatile("cp.async.commit_group;" ::: "memory"); }
DINLINE void cp_wait0()  { asm volatile("cp.async.wait_group 0;" ::: "memory"); }
DINLINE void cp_wait1()  { asm volatile("cp.async.wait_group 1;" ::: "memory"); }
// m16n8k16 fp16 mma: A row-major frag {a0..a3}, B col-major frag {b0,b1}, fp32 acc
DINLINE void mma_f16(float c[4], uint32_t a0, uint32_t a1, uint32_t a2, uint32_t a3,
                     uint32_t b0, uint32_t b1) {
    asm volatile(
        "mma.sync.aligned.m16n8k16.row.col.f32.f16.f16.f32 "
        "{%0,%1,%2,%3}, {%4,%5,%6,%7}, {%8,%9}, {%0,%1,%2,%3};"
        : "+f"(c[0]), "+f"(c[1]), "+f"(c[2]), "+f"(c[3])
        : "r"(a0), "r"(a1), "r"(a2), "r"(a3), "r"(b0), "r"(b1));
}

// async gather of tile t directly into padded fp16 A tile.
// 16 threads/row x 16B chunks: per warp-instr 2 rows x 256B = 4 lines (coalesced).
DINLINE void issue_gather(uint32_t* fbuf, const __half* __restrict__ Xh,
                          const int* __restrict__ im, int t, int r16, int ch) {
    #pragma unroll
    for (int pp = 0; pp < 8; pp++) {
        int r  = pp * 16 + r16;
        int p  = t * TILE_M + r;
        int pv = p < NPAIRS ? p : NPAIRS - 1;     // clamp; invalid rows never scattered
        const char* src = reinterpret_cast<const char*>(Xh + (size_t)im[pv] * C) + ch * 16;
        uint32_t dst = (uint32_t)__cvta_generic_to_shared(fbuf + r * ROWW) + ch * 16;
        cp_async16(dst, src);
    }
}

// ---------------------------------------------------------------- main kernel
// 296 persistent CTAs (2/SM) over (k, tile) jobs, contiguous blocks.
// 256 threads, 8 warps in 2(row-half) x 4(col-quarter): warp owns 64 rows x 32
// cols. fp16 B fragments (64 regs) resident. Activations pre-converted to fp16
// in global, so cp.async lands directly in the A tile: no convert phase, no
// staging, half the gather bytes. Per tile: barrier -> issue next -> wait ->
// barrier -> MMA+scatter. A rows padded to 68 words: MMA-read bank =
// (4g + tig) mod 32, all 32 lanes distinct. Scatter: quad butterfly -> red.v4.
__global__ void __launch_bounds__(THREADS, 2)
spconv_mma_kernel(const __half* __restrict__ Xh,  // [NPTS][C] fp16 activations
                  const __half* __restrict__ Wh,  // [KOFF][n][c] fp16
                  const int* __restrict__ in_map,
                  const int* __restrict__ out_map,
                  float* __restrict__ Y)
{
    extern __shared__ __align__(16) uint32_t SM[];
    uint32_t* fb[2] = { SM, SM + FBUF };

    const int tid = threadIdx.x;
    const int wid = tid >> 5, lid = tid & 31;
    const int g = lid >> 2, tig = lid & 3;         // groupID / thread-in-group
    const int rb = wid >> 2;                       // row half (0/1)
    const int n0 = (wid & 3) * 32;                 // col quarter base
    const int r16 = tid >> 4, ch = tid & 15;       // gather role: row-in-pass / chunk

    const int cta  = blockIdx.x;
    const int jbeg = cta * JBASE + (cta < JREM ? cta : JREM);
    const int jend = jbeg + JBASE + (cta < JREM ? 1 : 0);

    uint32_t bfr[8][4][2];                         // fp16 B fragments (64 regs)
    int kcur = -1;

    // prologue: async-gather first tile into buf0
    {
        int k0 = jbeg / NTILES, t0 = jbeg % NTILES;
        issue_gather(fb[0], Xh, in_map + k0 * NPAIRS, t0, r16, ch);
        cp_commit();
    }

    int c = 0;
    for (int jid = jbeg; jid < jend; jid++) {
        const int k = jid / NTILES, t = jid % NTILES;

        // ---- (re)load B fragments on k change ----
        if (k != kcur) {
            kcur = k;
            const __half* wk = Wh + (size_t)k * C * C;
            #pragma unroll
            for (int ks = 0; ks < 8; ks++)
                #pragma unroll
                for (int nb = 0; nb < 4; nb++) {
                    const __half* wrow = wk + (n0 + 8 * nb + g) * C + 16 * ks + 2 * tig;
                    bfr[ks][nb][0] = *reinterpret_cast<const uint32_t*>(wrow);
                    bfr[ks][nb][1] = *reinterpret_cast<const uint32_t*>(wrow + 8);
                }
        }

        // (A) all warps done reading fb[c^1] from previous iter -> safe to refill
        __syncthreads();
        if (jid + 1 < jend) {
            int k2 = (jid + 1) / NTILES, t2 = (jid + 1) % NTILES;
            issue_gather(fb[c ^ 1], Xh, in_map + k2 * NPAIRS, t2, r16, ch);
            cp_commit();
            cp_wait1();                            // own tile-t chunks arrived
        } else {
            cp_wait0();
        }
        // (B) everyone's tile-t chunks arrived
        __syncthreads();

        // ---- MMA + scatter on fb[c] ----
        const uint32_t* abuf = fb[c];
        const int* om = out_map + k * NPAIRS;
        #pragma unroll 1
        for (int mb = 0; mb < 4; mb++) {
            float acc[4][4] = {{0.f,0.f,0.f,0.f},{0.f,0.f,0.f,0.f},
                               {0.f,0.f,0.f,0.f},{0.f,0.f,0.f,0.f}};
            const int row_lo = rb * 64 + mb * 16 + g;
            const uint32_t* a_lo = abuf + row_lo * ROWW;
            const uint32_t* a_hi = a_lo + 8 * ROWW;
            #pragma unroll
            for (int ks = 0; ks < 8; ks++) {
                uint32_t a0 = a_lo[ks * 8 + tig];
                uint32_t a1 = a_hi[ks * 8 + tig];
                uint32_t a2 = a_lo[ks * 8 + tig + 4];
                uint32_t a3 = a_hi[ks * 8 + tig + 4];
                #pragma unroll
                for (int nb = 0; nb < 4; nb++)
                    mma_f16(acc[nb], a0, a1, a2, a3, bfr[ks][nb][0], bfr[ks][nb][1]);
            }

            // epilogue: quad butterfly -> red.v4 (16B per lane)
            int p_lo = t * TILE_M + row_lo;
            int p_hi = p_lo + 8;
            int d_lo = (p_lo < NPAIRS) ? om[p_lo] : -1;
            int d_hi = (p_hi < NPAIRS) ? om[p_hi] : -1;
            int dst  = (tig & 1) ? d_hi : d_lo;
            float* ybase = (dst >= 0)
                ? Y + (size_t)dst * C + n0 + ((tig >> 1) << 2) : nullptr;
            #pragma unroll
            for (int nb = 0; nb < 4; nb++) {
                // even lanes need partner's (c0,c1); odd lanes partner's (c2,c3)
                float s0 = (tig & 1) ? acc[nb][0] : acc[nb][2];
                float s1 = (tig & 1) ? acc[nb][1] : acc[nb][3];
                float r0 = __shfl_xor_sync(0xffffffffu, s0, 1);
                float r1 = __shfl_xor_sync(0xffffffffu, s1, 1);
                float q0 = (tig & 1) ? r0 : acc[nb][0];
                float q1 = (tig & 1) ? r1 : acc[nb][1];
                float q2 = (tig & 1) ? acc[nb][2] : r0;
                float q3 = (tig & 1) ? acc[nb][3] : r1;
                if (ybase) red_add_v4(ybase + 8 * nb, q0, q1, q2, q3);
            }
        }
        c ^= 1;
    }
}

// ---------------------------------------------------------------- small kernels
__global__ void wt_kernel(const float* __restrict__ W0, const float* __restrict__ W1) {
    int i = blockIdx.x * blockDim.x + threadIdx.x;       // over KOFF*C*C, layout [k][n][c]
    if (i >= KOFF * C * C) return;
    int k = i / (C * C);
    int rem = i % (C * C);
    int n = rem / C, c = rem % C;
    g_Wh[i] = __float2half_rn(W0[(size_t)k * C * C + c * C + n]);
    g_Wh[(size_t)KOFF * C * C + i] = __float2half_rn(W1[(size_t)k * C * C + c * C + n]);
}

__global__ void cvt_x_kernel(const float* __restrict__ X) {     // g_xh0 = fp16(X)
    int i = blockIdx.x * blockDim.x + threadIdx.x;       // float4 index
    if (i < NPTS * C / 4) {
        float4 v = reinterpret_cast<const float4*>(X)[i];
        __half2 a = __floats2half2_rn(v.x, v.y);
        __half2 b = __floats2half2_rn(v.z, v.w);
        uint2 o = { *reinterpret_cast<uint32_t*>(&a), *reinterpret_cast<uint32_t*>(&b) };
        reinterpret_cast<uint2*>(g_xh0)[i] = o;
    }
}

__global__ void cvt_h_relu_kernel() {                    // g_xh1 = fp16(relu(g_h))
    int i = blockIdx.x * blockDim.x + threadIdx.x;
    if (i < NPTS * C / 4) {
        float4 v = reinterpret_cast<const float4*>(g_h)[i];
        v.x = fmaxf(v.x, 0.f); v.y = fmaxf(v.y, 0.f);
        v.z = fmaxf(v.z, 0.f); v.w = fmaxf(v.w, 0.f);
        __half2 a = __floats2half2_rn(v.x, v.y);
        __half2 b = __floats2half2_rn(v.z, v.w);
        uint2 o = { *reinterpret_cast<uint32_t*>(&a), *reinterpret_cast<uint32_t*>(&b) };
        reinterpret_cast<uint2*>(g_xh1)[i] = o;
    }
}

__global__ void init_h_kernel(const float* __restrict__ b0) {
    int i = blockIdx.x * blockDim.x + threadIdx.x;       // float4 index
    if (i < NPTS * C / 4)
        reinterpret_cast<float4*>(g_h)[i] =
            reinterpret_cast<const float4*>(b0)[i & (C / 4 - 1)];
}

__global__ void init_out_kernel(const float* __restrict__ feat,
                                const float* __restrict__ b1,
                                float* __restrict__ out) {
    int i = blockIdx.x * blockDim.x + threadIdx.x;
    if (i < NPTS * C / 4) {
        float4 f = reinterpret_cast<const float4*>(feat)[i];
        float4 b = reinterpret_cast<const float4*>(b1)[i & (C / 4 - 1)];
        f.x += b.x; f.y += b.y; f.z += b.z; f.w += b.w;
        reinterpret_cast<float4*>(out)[i] = f;
    }
}

// ---------------------------------------------------------------- launch
extern "C" void kernel_launch(void* const* d_in, const int* in_sizes, int n_in,
                              void* d_out, int out_size) {
    const float* feat    = (const float*)d_in[0];
    const int*   in_map  = (const int*)  d_in[1];
    const int*   out_map = (const int*)  d_in[2];
    const float* W0      = (const float*)d_in[3];
    const float* b0      = (const float*)d_in[4];
    const float* W1      = (const float*)d_in[5];
    const float* b1      = (const float*)d_in[6];
    float*       out     = (float*)d_out;

    float*  h   = nullptr; cudaGetSymbolAddress((void**)&h,   g_h);
    __half* xh0 = nullptr; cudaGetSymbolAddress((void**)&xh0, g_xh0);
    __half* xh1 = nullptr; cudaGetSymbolAddress((void**)&xh1, g_xh1);
    __half* wh  = nullptr; cudaGetSymbolAddress((void**)&wh,  g_Wh);

    const int smem_bytes = 2 * FBUF * (int)sizeof(uint32_t);   // 69632
    cudaFuncSetAttribute(spconv_mma_kernel,
                         cudaFuncAttributeMaxDynamicSharedMemorySize, smem_bytes);

    const int nv4 = NPTS * C / 4;
    const int eb  = (nv4 + 255) / 256;

    wt_kernel<<<(KOFF * C * C + 255) / 256, 256>>>(W0, W1);
    cvt_x_kernel<<<eb, 256>>>(feat);

    // conv0: h = b0; h += scatter(gather(xh0) @ W0)
    init_h_kernel<<<eb, 256>>>(b0);
    spconv_mma_kernel<<<NCTA, THREADS, smem_bytes>>>(xh0, wh, in_map, out_map, h);

    // between convs: xh1 = fp16(relu(h))
    cvt_h_relu_kernel<<<eb, 256>>>();

    // conv1: out = x + b1; out += scatter(gather(xh1) @ W1)
    init_out_kernel<<<eb, 256>>>(feat, b1, out);
    spconv_mma_kernel<<<NCTA, THREADS, smem_bytes>>>(xh1, wh + (size_t)KOFF * C * C,
                                                    in_map, out_map, out);
}